// round 9
// baseline (speedup 1.0000x reference)
#include <cuda_runtime.h>
#include <cuda_bf16.h>
#include <cstdint>
#include <cstddef>

#define H 128
#define NTYPE 10
#define NREL 26
#define DEG_TOTAL 1828000
#define EDGE_TOTAL (26 * 300000)
#define BUF0_ROWS 414000
#define BUF1_ROWS 50000
#define TMP_ROWS 600000
#define AGG_ROWS 300000

// ---------------- scratch ----------------
__device__ float g_buf0[(size_t)BUF0_ROWS * H];
__device__ float g_buf1[(size_t)BUF1_ROWS * H];
__device__ float g_agg[(size_t)AGG_ROWS * H];     // bf16 hi/lo plane arena for dst-side
__device__ float g_tmp[(size_t)TMP_ROWS * H];
__device__ int   g_head[DEG_TOTAL];
__device__ int   g_next[EDGE_TOTAL];
__device__ float g_wsum[2 * NTYPE * H * H];
__device__ float g_bsum[2 * NTYPE * H];
__device__ __nv_bfloat16 g_wbf[72 * 2 * H * H];

__constant__ int c_rel_dst[NREL] = {1,0,2,0,3,0,4,0,5,0,6,0,7,6,6,5,7,5,5,4,3,4,8,2,9,2};

// ---------------- job descriptors ----------------
// GJob flags: 1=accumulate(red), 2=relu on A load, 4=A is pre-split bf16 planes
struct GJob { const float* A; const __nv_bfloat16* Wb; const float* bias; float* C;
              int M; int tile_base; int flags; int _pad; };
struct GBatch { GJob j[20]; int nj; };

// SJob flags: 1=relu on x, 2=red-accumulate fp32 out, 4=write pre-split bf16 planes
struct SJob { const float* x; const int* srcI; const int* head; const int* next;
              float* out; int n; int node_base; int flags; };
struct SBatch { SJob j[16]; int nj; };

struct CJob { const int* dstI; int* head; int* next; int E; int ebase; int _pad; };
struct CBatch { CJob j[22]; int nj; };

// ---------------- helpers ----------------
__device__ __forceinline__ uint32_t smem_to_u32(const void* p) {
    uint32_t a;
    asm("{ .reg .u64 t; cvta.to.shared.u64 t, %1; cvt.u32.u64 %0, t; }" : "=r"(a) : "l"(p));
    return a;
}

__device__ __forceinline__ void cvt8(const float* v, uint4& hi, uint4& lo) {
    uint32_t h[4], l[4];
    #pragma unroll
    for (int p = 0; p < 4; p++) {
        float a = v[2*p], b = v[2*p+1];
        __nv_bfloat16 ah = __float2bfloat16(a), bh = __float2bfloat16(b);
        float ar = a - __bfloat162float(ah), br = b - __bfloat162float(bh);
        __nv_bfloat16 al = __float2bfloat16(ar), bl2 = __float2bfloat16(br);
        h[p] = (uint32_t)__bfloat16_as_ushort(ah) | ((uint32_t)__bfloat16_as_ushort(bh) << 16);
        l[p] = (uint32_t)__bfloat16_as_ushort(al) | ((uint32_t)__bfloat16_as_ushort(bl2) << 16);
    }
    hi = make_uint4(h[0], h[1], h[2], h[3]);
    lo = make_uint4(l[0], l[1], l[2], l[3]);
}

#define LDMATRIX_X4(r0, r1, r2, r3, addr) \
    asm volatile("ldmatrix.sync.aligned.m8n8.x4.shared.b16 {%0,%1,%2,%3}, [%4];" \
                 : "=r"(r0), "=r"(r1), "=r"(r2), "=r"(r3) : "r"(addr))

#define MMA_BF16(c0, c1, c2, c3, a0, a1, a2, a3, b0, b1) \
    asm volatile("mma.sync.aligned.m16n8k16.row.col.f32.bf16.bf16.f32 " \
                 "{%0,%1,%2,%3}, {%4,%5,%6,%7}, {%8,%9}, {%0,%1,%2,%3};" \
                 : "+f"(c0), "+f"(c1), "+f"(c2), "+f"(c3) \
                 : "r"(a0), "r"(a1), "r"(a2), "r"(a3), "r"(b0), "r"(b1))

// ---------------- batched bf16 HMMA GEMM: 64x128 tile, 128 thr (4 warps), 2 CTA/SM ----
#define A_LD 136
#define SM_AH 0
#define SM_AL 17408
#define SM_BH 34816
#define SM_BL 69632
#define SM_BYTES 104448

__global__ void __launch_bounds__(128) gemm_batched(GBatch bat)
{
    extern __shared__ char smem[];
    const uint32_t sb = smem_to_u32(smem);
    const int tid = threadIdx.x, lane = tid & 31, wid = tid >> 5;

    int jb = 0;
    while (jb + 1 < bat.nj && (int)blockIdx.x >= bat.j[jb + 1].tile_base) jb++;
    const GJob& J = bat.j[jb];
    const int m0 = (blockIdx.x - J.tile_base) * 64;
    const int M = J.M;
    const int accumulate = J.flags & 1;
    const int doRelu = J.flags & 2;
    const int presplit = J.flags & 4;
    const float* bias = J.bias;
    float* C = J.C;

    // ---- stage A (64 rows) ----
    if (presplit) {
        const uint4* srcH = (const uint4*)J.A + (size_t)m0 * 16;
        const uint4* srcL = (const uint4*)((const __nv_bfloat16*)J.A + (size_t)M * H) + (size_t)m0 * 16;
        #pragma unroll
        for (int it = 0; it < 8; it++) {
            int idx = tid + it * 128;              // 1024 uint4 per plane
            int n = idx >> 4, q = idx & 15;
            *(uint4*)(smem + SM_AH + (size_t)n * (A_LD * 2) + q * 16) = srcH[idx];
            *(uint4*)(smem + SM_AL + (size_t)n * (A_LD * 2) + q * 16) = srcL[idx];
        }
    } else {
        const int r = tid >> 1;                    // 0..63
        const int co = (tid & 1) * 64;
        const int m = m0 + r;
        if (m < M) {
            const float4* Ar = (const float4*)(J.A + (size_t)m * H);
            #pragma unroll
            for (int c = 0; c < 64; c += 8) {
                float4 f0 = Ar[(co + c) >> 2], f1 = Ar[((co + c) >> 2) + 1];
                float v[8] = {f0.x,f0.y,f0.z,f0.w,f1.x,f1.y,f1.z,f1.w};
                if (doRelu) {
                    #pragma unroll
                    for (int j = 0; j < 8; j++) v[j] = fmaxf(v[j], 0.f);
                }
                uint4 hi, lo;
                cvt8(v, hi, lo);
                *(uint4*)(smem + SM_AH + (size_t)(r * A_LD + co + c) * 2) = hi;
                *(uint4*)(smem + SM_AL + (size_t)(r * A_LD + co + c) * 2) = lo;
            }
        } else {
            uint4 z = make_uint4(0,0,0,0);
            #pragma unroll
            for (int c = 0; c < 64; c += 8) {
                *(uint4*)(smem + SM_AH + (size_t)(r * A_LD + co + c) * 2) = z;
                *(uint4*)(smem + SM_AL + (size_t)(r * A_LD + co + c) * 2) = z;
            }
        }
    }

    // ---- stage B: 2048 uint4 per plane ----
    {
        const uint4* srcH = (const uint4*)J.Wb;
        const uint4* srcL = srcH + 2048;
        #pragma unroll
        for (int it = 0; it < 16; it++) {
            int idx = tid + it * 128;
            int n = idx >> 4, q = idx & 15;
            *(uint4*)(smem + SM_BH + (size_t)n * (A_LD * 2) + q * 16) = srcH[idx];
            *(uint4*)(smem + SM_BL + (size_t)n * (A_LD * 2) + q * 16) = srcL[idx];
        }
    }
    __syncthreads();

    // ---- warp tiling: 2x2 warps, each 32(m) x 64(n) ----
    const int warp_m = (wid >> 1) * 32;
    const int warp_n = (wid & 1) * 64;

    float acc[2][8][4];
    #pragma unroll
    for (int mt = 0; mt < 2; mt++)
        #pragma unroll
        for (int nt = 0; nt < 8; nt++)
            #pragma unroll
            for (int q = 0; q < 4; q++) acc[mt][nt][q] = 0.0f;

    const int lrow = lane & 15;
    const int lcol = (lane >> 4) << 3;

    uint32_t aoff[2], boff[4];
    #pragma unroll
    for (int mt = 0; mt < 2; mt++)
        aoff[mt] = (uint32_t)(((warp_m + mt * 16 + lrow) * A_LD + lcol) * 2);
    #pragma unroll
    for (int np = 0; np < 4; np++)
        boff[np] = (uint32_t)(((warp_n + np * 16 + lrow) * A_LD + lcol) * 2);

    #pragma unroll
    for (int ks = 0; ks < 8; ks++) {
        const uint32_t kb = ks * 32;
        uint32_t bh[16], bl[16], ah[2][4], al[2][4];
        #pragma unroll
        for (int np = 0; np < 4; np++) {
            LDMATRIX_X4(bh[np*4+0], bh[np*4+1], bh[np*4+2], bh[np*4+3], sb + SM_BH + boff[np] + kb);
            LDMATRIX_X4(bl[np*4+0], bl[np*4+1], bl[np*4+2], bl[np*4+3], sb + SM_BL + boff[np] + kb);
        }
        #pragma unroll
        for (int mt = 0; mt < 2; mt++) {
            LDMATRIX_X4(ah[mt][0], ah[mt][1], ah[mt][2], ah[mt][3], sb + SM_AH + aoff[mt] + kb);
            LDMATRIX_X4(al[mt][0], al[mt][1], al[mt][2], al[mt][3], sb + SM_AL + aoff[mt] + kb);
        }
        #pragma unroll
        for (int mt = 0; mt < 2; mt++) {
            #pragma unroll
            for (int np = 0; np < 4; np++) {
                const int n0 = np * 2, n1 = np * 2 + 1;
                // hh
                MMA_BF16(acc[mt][n0][0], acc[mt][n0][1], acc[mt][n0][2], acc[mt][n0][3],
                         ah[mt][0], ah[mt][1], ah[mt][2], ah[mt][3], bh[np*4+0], bh[np*4+2]);
                MMA_BF16(acc[mt][n1][0], acc[mt][n1][1], acc[mt][n1][2], acc[mt][n1][3],
                         ah[mt][0], ah[mt][1], ah[mt][2], ah[mt][3], bh[np*4+1], bh[np*4+3]);
                // lh
                MMA_BF16(acc[mt][n0][0], acc[mt][n0][1], acc[mt][n0][2], acc[mt][n0][3],
                         al[mt][0], al[mt][1], al[mt][2], al[mt][3], bh[np*4+0], bh[np*4+2]);
                MMA_BF16(acc[mt][n1][0], acc[mt][n1][1], acc[mt][n1][2], acc[mt][n1][3],
                         al[mt][0], al[mt][1], al[mt][2], al[mt][3], bh[np*4+1], bh[np*4+3]);
                // hl
                MMA_BF16(acc[mt][n0][0], acc[mt][n0][1], acc[mt][n0][2], acc[mt][n0][3],
                         ah[mt][0], ah[mt][1], ah[mt][2], ah[mt][3], bl[np*4+0], bl[np*4+2]);
                MMA_BF16(acc[mt][n1][0], acc[mt][n1][1], acc[mt][n1][2], acc[mt][n1][3],
                         ah[mt][0], ah[mt][1], ah[mt][2], ah[mt][3], bl[np*4+1], bl[np*4+3]);
            }
        }
    }

    // ---- epilogue ----
    const int qrow = lane >> 2;
    const int qcol = (lane & 3) * 2;
    #pragma unroll
    for (int mt = 0; mt < 2; mt++) {
        #pragma unroll
        for (int half = 0; half < 2; half++) {
            const int m = m0 + warp_m + mt * 16 + qrow + half * 8;
            if (m < M) {
                float* cp = C + (size_t)m * H;
                #pragma unroll
                for (int nt = 0; nt < 8; nt++) {
                    const int c = warp_n + nt * 8 + qcol;
                    float v0 = acc[mt][nt][half * 2 + 0];
                    float v1 = acc[mt][nt][half * 2 + 1];
                    if (accumulate) {
                        asm volatile("red.global.add.v2.f32 [%0], {%1,%2};"
                                     :: "l"(cp + c), "f"(v0), "f"(v1) : "memory");
                    } else {
                        if (bias) { v0 += bias[c]; v1 += bias[c + 1]; }
                        *(float2*)(cp + c) = make_float2(v0, v1);
                    }
                }
            }
        }
    }
}

// ---------------- Wr / bias reduction ----------------
__global__ void __launch_bounds__(256) wsum_kernel(
    const float* __restrict__ Wr, const float* __restrict__ bl,
    float* __restrict__ wsum, float* __restrict__ bsum)
{
    int layer = blockIdx.x / NTYPE;
    int t = blockIdx.x % NTYPE;
    const float* base = Wr + (size_t)layer * NREL * H * H;
    float* outw = wsum + ((size_t)layer * NTYPE + t) * H * H;
    for (int e = threadIdx.x; e < H * H; e += 256) {
        float a = 0.f;
        #pragma unroll
        for (int r = 0; r < NREL; r++)
            if (c_rel_dst[r] == t) a += base[(size_t)r * H * H + e];
        outw[e] = a;
    }
    if (threadIdx.x < H) {
        float a = 0.f;
        #pragma unroll
        for (int r = 0; r < NREL; r++)
            if (c_rel_dst[r] == t) a += bl[((size_t)layer * NREL + r) * H + threadIdx.x];
        bsum[((size_t)layer * NTYPE + t) * H + threadIdx.x] = a;
    }
}

// ---------------- weight conversion ----------------
__global__ void __launch_bounds__(256) wcvt_kernel(
    const float* __restrict__ wsum, const float* __restrict__ Wl,
    __nv_bfloat16* __restrict__ wbf)
{
    int m = blockIdx.x;   // 0..71
    const float* src = (m < 20) ? (wsum + (size_t)m * H * H)
                                : (Wl + (size_t)(m - 20) * H * H);
    __nv_bfloat16* hi = wbf + (size_t)m * 2 * H * H;
    __nv_bfloat16* lo = hi + H * H;
    for (int idx = threadIdx.x; idx < H * H; idx += 256) {
        int k = idx >> 7, n = idx & 127;
        float w = src[idx];
        __nv_bfloat16 wh = __float2bfloat16(w);
        float wr = w - __bfloat162float(wh);
        hi[n * H + k] = wh;
        lo[n * H + k] = __float2bfloat16(wr);
    }
}

// ---------------- batched chain build ----------------
__global__ void __launch_bounds__(256) build_chain_batched(CBatch bat, int total)
{
    int g = blockIdx.x * blockDim.x + threadIdx.x;
    if (g >= total) return;
    int jb = 0;
    while (jb + 1 < bat.nj && g >= bat.j[jb + 1].ebase) jb++;
    const CJob& J = bat.j[jb];
    int e = g - J.ebase;
    J.next[e] = atomicExch(J.head + __ldg(J.dstI + e), e);
}

// ---------------- per-node finish for gather ----------------
__device__ __forceinline__ void gather_finish(const SJob& J, int node, int lane,
                                              float4 acc, float cnt)
{
    if (node >= J.n) return;
    float sc = 1.0f / fmaxf(cnt, 1.0f);
    acc.x *= sc; acc.y *= sc; acc.z *= sc; acc.w *= sc;
    if (J.flags & 4) {
        float v[4] = {acc.x, acc.y, acc.z, acc.w};
        uint32_t h[2], l[2];
        #pragma unroll
        for (int p = 0; p < 2; p++) {
            float a = v[2*p], b = v[2*p+1];
            __nv_bfloat16 ah = __float2bfloat16(a), bh = __float2bfloat16(b);
            float ar = a - __bfloat162float(ah), br = b - __bfloat162float(bh);
            h[p] = (uint32_t)__bfloat16_as_ushort(ah) | ((uint32_t)__bfloat16_as_ushort(bh) << 16);
            l[p] = (uint32_t)__bfloat16_as_ushort(__float2bfloat16(ar))
                 | ((uint32_t)__bfloat16_as_ushort(__float2bfloat16(br)) << 16);
        }
        __nv_bfloat16* hi = (__nv_bfloat16*)J.out;
        *(uint2*)(hi + (size_t)node * H + lane * 4) = make_uint2(h[0], h[1]);
        *(uint2*)(hi + (size_t)J.n * H + (size_t)node * H + lane * 4) = make_uint2(l[0], l[1]);
    } else if (J.flags & 2) {
        float* p = J.out + (size_t)node * H + lane * 4;
        asm volatile("red.global.add.v4.f32 [%0], {%1,%2,%3,%4};"
                     :: "l"(p), "f"(acc.x), "f"(acc.y), "f"(acc.z), "f"(acc.w) : "memory");
    } else {
        *(float4*)(J.out + (size_t)node * H + lane * 4) = acc;
    }
}

// ---------------- batched chain gather: 4 interleaved chains per warp (MLP=4) --------
__global__ void __launch_bounds__(256) gather_batched(SBatch bat, int totalGroups)
{
    int grp = blockIdx.x * 8 + (threadIdx.x >> 5);
    if (grp >= totalGroups) return;
    const int idx0 = grp * 4;
    int jb = 0;
    while (jb + 1 < bat.nj && idx0 >= bat.j[jb + 1].node_base) jb++;
    const SJob& J = bat.j[jb];
    const int lane = threadIdx.x & 31;
    const int doRelu = J.flags & 1;
    const float* x = J.x;
    const int* srcI = J.srcI;
    const int* next = J.next;
    const int n0 = idx0 - J.node_base;

    int e0 = (n0 + 0 < J.n) ? __ldg(J.head + n0 + 0) : -1;
    int e1 = (n0 + 1 < J.n) ? __ldg(J.head + n0 + 1) : -1;
    int e2 = (n0 + 2 < J.n) ? __ldg(J.head + n0 + 2) : -1;
    int e3 = (n0 + 3 < J.n) ? __ldg(J.head + n0 + 3) : -1;
    float4 a0 = make_float4(0,0,0,0), a1 = a0, a2 = a0, a3 = a0;
    float c0 = 0, c1 = 0, c2 = 0, c3 = 0;

    while (e0 >= 0 || e1 >= 0 || e2 >= 0 || e3 >= 0) {
        if (e0 >= 0) {
            int s = __ldg(srcI + e0); int nx = __ldg(next + e0);
            float4 v = __ldg(((const float4*)(x + (size_t)s * H)) + lane);
            if (doRelu) { v.x=fmaxf(v.x,0.f); v.y=fmaxf(v.y,0.f); v.z=fmaxf(v.z,0.f); v.w=fmaxf(v.w,0.f); }
            a0.x += v.x; a0.y += v.y; a0.z += v.z; a0.w += v.w; c0 += 1.f; e0 = nx;
        }
        if (e1 >= 0) {
            int s = __ldg(srcI + e1); int nx = __ldg(next + e1);
            float4 v = __ldg(((const float4*)(x + (size_t)s * H)) + lane);
            if (doRelu) { v.x=fmaxf(v.x,0.f); v.y=fmaxf(v.y,0.f); v.z=fmaxf(v.z,0.f); v.w=fmaxf(v.w,0.f); }
            a1.x += v.x; a1.y += v.y; a1.z += v.z; a1.w += v.w; c1 += 1.f; e1 = nx;
        }
        if (e2 >= 0) {
            int s = __ldg(srcI + e2); int nx = __ldg(next + e2);
            float4 v = __ldg(((const float4*)(x + (size_t)s * H)) + lane);
            if (doRelu) { v.x=fmaxf(v.x,0.f); v.y=fmaxf(v.y,0.f); v.z=fmaxf(v.z,0.f); v.w=fmaxf(v.w,0.f); }
            a2.x += v.x; a2.y += v.y; a2.z += v.z; a2.w += v.w; c2 += 1.f; e2 = nx;
        }
        if (e3 >= 0) {
            int s = __ldg(srcI + e3); int nx = __ldg(next + e3);
            float4 v = __ldg(((const float4*)(x + (size_t)s * H)) + lane);
            if (doRelu) { v.x=fmaxf(v.x,0.f); v.y=fmaxf(v.y,0.f); v.z=fmaxf(v.z,0.f); v.w=fmaxf(v.w,0.f); }
            a3.x += v.x; a3.y += v.y; a3.z += v.z; a3.w += v.w; c3 += 1.f; e3 = nx;
        }
    }

    gather_finish(J, n0 + 0, lane, a0, c0);
    gather_finish(J, n0 + 1, lane, a1, c1);
    gather_finish(J, n0 + 2, lane, a2, c2);
    gather_finish(J, n0 + 3, lane, a3, c3);
}

// ---------------- final linear ----------------
__global__ void __launch_bounds__(128) final_kernel(
    const float* __restrict__ X, const float* __restrict__ W,
    const float* __restrict__ b, float* __restrict__ out, int M)
{
    __shared__ float Ws[H * 64];
    __shared__ float bs[64];
    for (int i = threadIdx.x; i < H * 64; i += 128) Ws[i] = W[i];
    if (threadIdx.x < 64) bs[threadIdx.x] = b[threadIdx.x];
    __syncthreads();
    int m = blockIdx.x * 128 + threadIdx.x;
    if (m >= M) return;
    float acc[64];
    #pragma unroll
    for (int j = 0; j < 64; j++) acc[j] = bs[j];
    const float* x = X + (size_t)m * H;
    for (int k = 0; k < H; k++) {
        float xv = fmaxf(x[k], 0.f);
        #pragma unroll
        for (int j = 0; j < 64; j++) acc[j] += xv * Ws[k * 64 + j];
    }
    float* o = out + (size_t)m * 64;
    #pragma unroll
    for (int j = 0; j < 64; j++) o[j] = acc[j];
}

// ---------------- host ----------------
static const int NN[NTYPE]   = {50000,2000,80000,10000,2000,150000,120000,100000,60000,40000};
static const int OFFS[NTYPE] = {0,50000,52000,132000,142000,144000,294000,414000,514000,574000};
static const int R_SRC[NREL] = {0,1,0,2,0,3,0,4,0,5,0,6,6,7,5,6,5,7,4,5,4,3,2,8,2,9};
static const int R_DST[NREL] = {1,0,2,0,3,0,4,0,5,0,6,0,7,6,6,5,7,5,5,4,3,4,8,2,9,2};
static const int R_EI[NREL]  = {10,10,11,11,12,12,13,13,14,14,15,15,16,16,17,17,18,18,19,19,20,20,21,21,22,22};
static const int R_FLIP[NREL]= {0,1,0,1,0,1,0,1,0,1,0,1,0,1,0,1,0,1,0,1,0,1,0,1,0,1};

static inline int l1_type_needed(int t) { return t < 7; }
static inline int l1_rel_needed(int r)  { return R_DST[r] < 7; }
static inline int l2_rel_needed(int r)  { return R_DST[r] == 0; }

extern "C" void kernel_launch(void* const* d_in, const int* in_sizes, int n_in,
                              void* d_out, int out_size)
{
    const float* Wl   = (const float*)d_in[23];
    const float* bl   = (const float*)d_in[24];
    const float* Wr   = (const float*)d_in[25];
    const float* linW = (const float*)d_in[26];
    const float* linb = (const float*)d_in[27];

    float *buf0, *buf1, *agg, *tmp, *wsum, *bsum;
    int *head, *nxt;
    __nv_bfloat16* wbf;
    cudaGetSymbolAddress((void**)&buf0, g_buf0);
    cudaGetSymbolAddress((void**)&buf1, g_buf1);
    cudaGetSymbolAddress((void**)&agg,  g_agg);
    cudaGetSymbolAddress((void**)&tmp,  g_tmp);
    cudaGetSymbolAddress((void**)&head, g_head);
    cudaGetSymbolAddress((void**)&nxt,  g_next);
    cudaGetSymbolAddress((void**)&wsum, g_wsum);
    cudaGetSymbolAddress((void**)&bsum, g_bsum);
    cudaGetSymbolAddress((void**)&wbf,  g_wbf);

    cudaFuncSetAttribute(gemm_batched, cudaFuncAttributeMaxDynamicSharedMemorySize, SM_BYTES);

    int DEGOFF[NREL], EOFF[NREL];
    {
        int a = 0, b2 = 0;
        for (int r = 0; r < NREL; r++) {
            DEGOFF[r] = a; a += NN[R_DST[r]];
            EOFF[r] = b2; b2 += in_sizes[R_EI[r]] / 2;
        }
    }

    // ---- prep ----
    wsum_kernel<<<2 * NTYPE, 256>>>(Wr, bl, wsum, bsum);
    wcvt_kernel<<<72, 256>>>(wsum, Wl, wbf);
    cudaMemsetAsync(head, 0xFF, (size_t)DEG_TOTAL * sizeof(int), 0);

    {
        CBatch cb; cb.nj = 0;
        int etot = 0;
        for (int r = 0; r < NREL; r++) {
            if (!l1_rel_needed(r) && !l2_rel_needed(r)) continue;
            int ii = R_EI[r];
            const int* ei = (const int*)d_in[ii];
            int E = in_sizes[ii] / 2;
            const int* dstI = R_FLIP[r] ? ei : ei + E;
            CJob& J = cb.j[cb.nj++];
            J.dstI = dstI; J.head = head + DEGOFF[r]; J.next = nxt + EOFF[r];
            J.E = E; J.ebase = etot;
            etot += E;
        }
        build_chain_batched<<<(etot + 255) / 256, 256>>>(cb, etot);
    }

    const float* cur[NTYPE];
    for (int t = 0; t < NTYPE; t++) cur[t] = (const float*)d_in[t];
    float* bufs[2] = {buf0, buf1};

    for (int layer = 0; layer < 2; layer++) {
        float* outbuf = bufs[layer];
        const int lrelu = (layer == 1);
        const int aflags = lrelu ? 2 : 0;

        GBatch ga; ga.nj = 0; int gaTiles = 0;
        SBatch sd; sd.nj = 0; int sdNodes = 0;   // dst-side gathers (presplit stores)
        SBatch ss; ss.nj = 0; int ssNodes = 0;   // src-side gathers (red into out)
        GBatch gb; gb.nj = 0; int gbTiles = 0;
        size_t tmpoff = 0, aggoff = 0;

        // self terms
        for (int t = 0; t < NTYPE; t++) {
            if (layer == 0 ? !l1_type_needed(t) : (t != 0)) continue;
            int outoff = (layer == 0) ? OFFS[t] : 0;
            GJob& J = ga.j[ga.nj++];
            J.A = cur[t];
            J.Wb = wbf + (size_t)(layer * NTYPE + t) * 2 * H * H;
            J.bias = bsum + ((size_t)layer * NTYPE + t) * H;
            J.C = outbuf + (size_t)outoff * H;
            J.M = NN[t]; J.tile_base = gaTiles; J.flags = aflags;
            gaTiles += (NN[t] + 63) / 64;
        }

        // neighbor terms
        for (int r = 0; r < NREL; r++) {
            if (layer == 0 ? !l1_rel_needed(r) : !l2_rel_needed(r)) continue;
            int s = R_SRC[r], d = R_DST[r], ii = R_EI[r];
            const int* ei = (const int*)d_in[ii];
            int E = in_sizes[ii] / 2;
            const int* srcI = R_FLIP[r] ? ei + E : ei;
            int nd = NN[d];
            int outoff = (layer == 0) ? OFFS[d] : 0;
            const __nv_bfloat16* wmat = wbf + (size_t)(20 + layer * NREL + r) * 2 * H * H;

            if (NN[s] < nd) {
                // src-side: GEMM into tmp, gather-red into out
                float* tp = tmp + tmpoff * H;
                tmpoff += NN[s];
                GJob& J = ga.j[ga.nj++];
                J.A = cur[s]; J.Wb = wmat; J.bias = nullptr; J.C = tp;
                J.M = NN[s]; J.tile_base = gaTiles; J.flags = aflags;
                gaTiles += (NN[s] + 63) / 64;

                ssNodes = (ssNodes + 3) & ~3;
                SJob& S = ss.j[ss.nj++];
                S.x = tp; S.srcI = srcI; S.head = head + DEGOFF[r]; S.next = nxt + EOFF[r];
                S.out = outbuf + (size_t)outoff * H; S.n = nd;
                S.node_base = ssNodes; S.flags = 2;
                ssNodes += nd;
            } else {
                // dst-side: gather mean -> pre-split bf16 planes, then GEMM-red
                float* ap = agg + aggoff * H;
                aggoff += nd;
                sdNodes = (sdNodes + 3) & ~3;
                SJob& S = sd.j[sd.nj++];
                S.x = cur[s]; S.srcI = srcI; S.head = head + DEGOFF[r]; S.next = nxt + EOFF[r];
                S.out = ap; S.n = nd;
                S.node_base = sdNodes; S.flags = (lrelu ? 1 : 0) | 4;
                sdNodes += nd;

                GJob& J = gb.j[gb.nj++];
                J.A = ap; J.Wb = wmat; J.bias = nullptr;
                J.C = outbuf + (size_t)outoff * H;
                J.M = nd; J.tile_base = gbTiles; J.flags = 1 | 4;
                gbTiles += (nd + 63) / 64;
            }
        }

        int sdGroups = (sdNodes + 3) / 4;
        int ssGroups = (ssNodes + 3) / 4;
        // dst-gathers first (independent of ga), then ga, src-gathers, gb
        gather_batched<<<(sdGroups + 7) / 8, 256>>>(sd, sdGroups);
        gemm_batched<<<gaTiles, 128, SM_BYTES>>>(ga);
        gather_batched<<<(ssGroups + 7) / 8, 256>>>(ss, ssGroups);
        gemm_batched<<<gbTiles, 128, SM_BYTES>>>(gb);

        if (layer == 0)
            for (int t = 0; t < 7; t++) cur[t] = buf0 + (size_t)OFFS[t] * H;
    }

    final_kernel<<<(BUF1_ROWS + 127) / 128, 128>>>(buf1, linW, linb, (float*)d_out, BUF1_ROWS);
}